// round 15
// baseline (speedup 1.0000x reference)
#include <cuda_runtime.h>
#include <cstdint>
#include <math.h>

#define B_   16
#define T_   512
#define P_   2048
#define SN   256
#define SD   1024
#define NC_DEN 128
#define NC_NUM 8
#define NCTA (NC_DEN + NC_NUM)
#define NTHR 512
#define RSMASK 7            // rescale when (t & RSMASK) == 0

// -------------------- persistent device scratch (no runtime allocation) -----
__device__ __align__(16) float g_qden[2][SD * 16];
__device__ __align__(16) float g_qnum[2][SN * 16];
__device__ float g_part[NCTA][16];
__device__ double g_lp[2][16];
__device__ unsigned long long g_bar;   // monotonic; survives graph replays

__device__ __forceinline__ unsigned long long ld_relaxed_u64(const unsigned long long* p) {
    unsigned long long v;
    asm volatile("ld.relaxed.gpu.u64 %0, [%1];" : "=l"(v) : "l"(p));
    return v;
}

// -------------------- grid barrier (136 CTAs co-resident) -------------------
__device__ __forceinline__ void grid_barrier() {
    __syncthreads();
    if (threadIdx.x == 0) {
        __threadfence();
        unsigned long long old = atomicAdd(&g_bar, 1ULL);
        unsigned long long target = (old / NCTA + 1ULL) * (unsigned long long)NCTA;
        while (ld_relaxed_u64(&g_bar) < target) { }
        __threadfence();
    }
    __syncthreads();
}

// -------------------- packed f32x2 helpers -----------------------------------
__device__ __forceinline__ void fma2(long long& a, long long q, long long e) {
    asm("fma.rn.f32x2 %0, %1, %2, %0;" : "+l"(a) : "l"(q), "l"(e));
}
__device__ __forceinline__ void add2(long long& a, long long bb) {
    asm("add.rn.f32x2 %0, %1, %0;" : "+l"(a) : "l"(bb));
}

// -------------------- one FSM (num or den), one column tile per CTA ---------
// q layout in global: q[i*16 + b]; longlong2 index = i*4 + bq (b = 4bq..4bq+3)
template <int S, int JT, int JQ, int PROB>
__device__ void run_fsm(const float* __restrict__ input,
                        const int*   __restrict__ seqlen,
                        const float* __restrict__ initv,
                        const float* __restrict__ trans,
                        const float* __restrict__ finalv,
                        const int*   __restrict__ pdf,
                        float* q0buf, float* q1buf,
                        int tileIdx, bool tracker, int ctaFirst, int nCtaProb)
{
    constexpr int GRP   = 4 * JQ;           // den: 4,   num: 32
    constexpr int NSEG  = NTHR / GRP;       // den: 128, num: 16
    constexpr int ILEN  = S / NSEG;         // den: 8,   num: 16
    constexpr int NOUT  = 16 * JT;          // den: 128, num: 512
    constexpr int ROWP  = NOUT + 8;         // den: 136, num: 520
    constexpr int SPLIT = NTHR / NOUT;      // den: 4,   num: 1
    constexpr int SEGPT = NSEG / SPLIT;     // den: 32,  num: 16
    constexpr int EROW  = 2 * JT;           // E words per i row (16 / 64)
    constexpr int JTH   = JT / JQ;          // j's per thread (8 / 4)

    const int tid   = threadIdx.x;
    const int lane  = tid & 31;
    const int warp  = tid >> 5;
    const int jbase = tileIdx * JT;

    extern __shared__ float sm[];
    float* Es    = sm;                       // 16384 words (both FSMs)
    float* red   = sm + 16384;               // 17408 words
    float* part  = red + 17408;              // 544 words
    float* ssw   = part + 544;               // 256 words (16 warps x 16 b)
    int*   sm_len = (int*)(ssw + 256);       // 16 ints

    if (tid < 16) sm_len[tid] = seqlen[tid];

    // ---- E tile, duplicated pairs {e,e}, conflict-free permuted layout ----
    for (int k = tid; k < S * JT; k += NTHR) {
        int i = k / JT, jl = k % JT;
        float e = expf(__ldg(&trans[(size_t)i * S + jbase + jl]));
        int addr;
        if (JQ == 1) {  // den: blocks of 8 i; slot-rotate by g&3, row-parity by g>>2
            int g  = (i >> 3) & 7;
            int li = i & 7;
            int sg = jl >> 1;
            addr = ((i >> 3) << 7) + ((li ^ (g >> 2)) << 4)
                 + (((sg ^ (g & 3)) << 2)) + ((jl & 1) << 1);
        } else {        // num: slot permutation sigma ^ (sigma>>3) within 64-word row
            int sg = jl >> 1;
            int sp = sg ^ (sg >> 3);
            addr = i * EROW + (sp << 2) + ((jl & 1) << 1);
        }
        Es[addr] = e; Es[addr + 1] = e;
    }

    // output-thread mapping: tid -> (b = tid%16, j = tid/16)
    int b = 0, jg = 0, pdfj = 0;
    float qlast = 0.f;
    if (tid < NOUT) {
        b  = tid & 15;
        jg = jbase + (tid >> 4);
        pdfj = __ldg(&pdf[jg]);
        qlast = expf(__ldg(&initv[jg]) + __ldg(&input[(size_t)b * T_ * P_ + pdfj]));
        __stcg(&q0buf[(size_t)jbase * 16 + tid], qlast);
    }

    double Creg = 0.0;                       // tracker-only running log-offset

    // GEMM thread coords
    const int jq   = tid % JQ;               // den: 0, num: 0..7
    const int bq   = (tid / JQ) & 3;
    const int iseg = tid / GRP;
    const int jb0  = JTH * jq;               // this thread's first local j

    // den read params
    const int gD = iseg & 7, pD = gD >> 2, aD = gD & 3;
    // num read params (slot indices)
    const int s0N = (2 * jq) ^ (jq >> 2);
    const int s1N = (2 * jq + 1) ^ (jq >> 2);

    for (int t = 1; t < T_; ++t) {
        // prefetch this step's emission BEFORE the barrier
        float ev = 0.f;
        if (tid < NOUT) ev = __ldg(&input[((size_t)b * T_ + t) * P_ + pdfj]);

        grid_barrier();                      // q(t-1) globally visible
        const float* qprev = (t & 1) ? q0buf : q1buf;
        float*       qcur  = (t & 1) ? q1buf : q0buf;
        const bool rsc = ((t & RSMASK) == 0);

        long long ax[JTH], ay[JTH];
        #pragma unroll
        for (int j = 0; j < JTH; j++) { ax[j] = 0; ay[j] = 0; }
        long long sA = 0, sB = 0;
        const longlong2* qp = (const longlong2*)qprev;

        #pragma unroll
        for (int ii = 0; ii < ILEN; ii++) {
            int i = iseg * ILEN + ii;
            longlong2 qv = __ldcg(qp + i * 4 + bq);
            if (JQ == 1) {                    // den: all 8 j per thread
                const float* er = Es + (iseg << 7) + ((ii ^ pD) << 4);
                longlong2 e0 = *(const longlong2*)(er + ((0 ^ aD) << 2));
                longlong2 e1 = *(const longlong2*)(er + ((1 ^ aD) << 2));
                longlong2 e2 = *(const longlong2*)(er + ((2 ^ aD) << 2));
                longlong2 e3 = *(const longlong2*)(er + ((3 ^ aD) << 2));
                fma2(ax[0], qv.x, e0.x); fma2(ay[0], qv.y, e0.x);
                fma2(ax[1], qv.x, e0.y); fma2(ay[1], qv.y, e0.y);
                fma2(ax[2], qv.x, e1.x); fma2(ay[2], qv.y, e1.x);
                fma2(ax[3], qv.x, e1.y); fma2(ay[3], qv.y, e1.y);
                fma2(ax[4], qv.x, e2.x); fma2(ay[4], qv.y, e2.x);
                fma2(ax[5], qv.x, e2.y); fma2(ay[5], qv.y, e2.y);
                fma2(ax[6], qv.x, e3.x); fma2(ay[6], qv.y, e3.x);
                fma2(ax[7], qv.x, e3.y); fma2(ay[7], qv.y, e3.y);
            } else {                          // num: 4 j per thread
                const float* er = Es + i * EROW;
                longlong2 eA = *(const longlong2*)(er + (s0N << 2));
                longlong2 eB = *(const longlong2*)(er + (s1N << 2));
                fma2(ax[0], qv.x, eA.x); fma2(ay[0], qv.y, eA.x);
                fma2(ax[1], qv.x, eA.y); fma2(ay[1], qv.y, eA.y);
                fma2(ax[2], qv.x, eB.x); fma2(ay[2], qv.y, eB.x);
                fma2(ax[3], qv.x, eB.y); fma2(ay[3], qv.y, eB.y);
            }
            if (rsc) { add2(sA, qv.x); add2(sB, qv.y); }
        }

        // per-b partial sums -> ssw[warp][b] (rescale steps only)
        if (rsc) {
            if (JQ == 1) {                    // reduce over lane bits 2..4 (g)
                long long tq;
                #pragma unroll
                for (int m = 4; m < 32; m <<= 1) {
                    tq = __shfl_xor_sync(0xffffffffu, sA, m); add2(sA, tq);
                    tq = __shfl_xor_sync(0xffffffffu, sB, m); add2(sB, tq);
                }
                if (lane < 4) {
                    *(long long*)&ssw[warp * 16 + 4 * lane]     = sA;
                    *(long long*)&ssw[warp * 16 + 4 * lane + 2] = sB;
                }
            } else {                          // all jq hold identical sums
                if ((lane & 7) == 0) {
                    int bql = lane >> 3;
                    *(long long*)&ssw[warp * 16 + 4 * bql]     = sA;
                    *(long long*)&ssw[warp * 16 + 4 * bql + 2] = sB;
                }
            }
        }

        // store partials: red[iseg][j*16 + b-range]
        {
            float* rb = red + iseg * ROWP + jb0 * 16 + bq * 4;
            #pragma unroll
            for (int j = 0; j < JTH; j++) {
                longlong2 v; v.x = ax[j]; v.y = ay[j];
                *(longlong2*)(rb + j * 16) = v;
            }
        }
        __syncthreads();

        // stage A: each thread sums SEGPT segments for one output
        float dot = 0.f;
        {
            int out = tid % NOUT, g2 = tid / NOUT;
            const float* rr = red + (g2 * SEGPT) * ROWP + out;
            float p = 0.f;
            #pragma unroll
            for (int s2 = 0; s2 < SEGPT; s2++) p += rr[s2 * ROWP];
            if (SPLIT > 1) part[g2 * 136 + out] = p; else dot = p;
        }
        if (SPLIT > 1) {
            __syncthreads();
            if (tid < NOUT) {
                dot = part[tid];
                #pragma unroll
                for (int g = 1; g < SPLIT; g++) dot += part[g * 136 + tid];
            }
        }

        // q(t) update; rescale every 8 steps
        if (tid < NOUT) {
            float qn;
            if (rsc) {
                float s = 0.f;
                #pragma unroll
                for (int w2 = 0; w2 < 16; w2++) s += ssw[w2 * 16 + b];
                float inv = 1.0f / s;
                qn = (t < sm_len[b]) ? dot * inv * expf(ev) : qlast * inv;
                if (tracker && tid < 16) Creg += (double)logf(s);
            } else {
                qn = (t < sm_len[b]) ? dot * expf(ev) : qlast;
            }
            qlast = qn;
            __stcg(&qcur[(size_t)jbase * 16 + tid], qn);
        }
    }

    // ---------------- final: logprob_b = C_b + log( sum_j q_T[b,j]*exp(final_j) )
    __syncthreads();
    if (tid < NOUT) red[tid] = qlast * expf(__ldg(&finalv[jg]));
    __syncthreads();
    if (tid < 16) {
        float p = 0.f;
        #pragma unroll
        for (int c = 0; c < JT; c++) p += red[c * 16 + tid];
        g_part[blockIdx.x][tid] = p;
    }
    __threadfence();
    grid_barrier();
    if (tracker && tid < 16) {
        double tot = 0.0;
        for (int c = 0; c < nCtaProb; c++)
            tot += (double)__ldcg(&g_part[ctaFirst + c][tid]);
        g_lp[PROB][tid] = Creg + log(tot);
    }
    __threadfence();
    grid_barrier();
}

// -------------------- kernel ------------------------------------------------
__global__ void __launch_bounds__(NTHR, 1)
lfmmi_kernel(const float* input, const int* seqlen,
             const float* n_init, const float* n_trans, const float* n_final, const int* n_pdf,
             const float* d_init, const float* d_trans, const float* d_final, const int* d_pdf,
             float* out)
{
    int cta = blockIdx.x;
    if (cta < NC_DEN) {
        run_fsm<SD, 8, 1, 0>(input, seqlen, d_init, d_trans, d_final, d_pdf,
                             g_qden[0], g_qden[1], cta, cta == 0, 0, NC_DEN);
    } else {
        run_fsm<SN, 32, 8, 1>(input, seqlen, n_init, n_trans, n_final, n_pdf,
                              g_qnum[0], g_qnum[1], cta - NC_DEN, cta == NC_DEN,
                              NC_DEN, NC_NUM);
    }
    if (cta == 0 && threadIdx.x == 0) {
        double dsum = 0.0, nsum = 0.0;
        for (int bb = 0; bb < 16; ++bb) {
            dsum += __ldcg(&g_lp[0][bb]);
            nsum += __ldcg(&g_lp[1][bb]);
        }
        out[0] = (float)(-(nsum - dsum));
    }
}

// -------------------- launch -------------------------------------------------
extern "C" void kernel_launch(void* const* d_in, const int* in_sizes, int n_in,
                              void* d_out, int out_size)
{
    (void)in_sizes; (void)n_in; (void)out_size;
    // words: Es 16384 + red 17408 + part 544 + ssw 256 + len 16 = 34608
    const size_t smem = 34608 * sizeof(float);   // 138,432 B
    cudaFuncSetAttribute(lfmmi_kernel,
                         cudaFuncAttributeMaxDynamicSharedMemorySize, (int)smem);
    lfmmi_kernel<<<NCTA, NTHR, smem>>>(
        (const float*)d_in[0], (const int*)d_in[1],
        (const float*)d_in[2], (const float*)d_in[3], (const float*)d_in[4], (const int*)d_in[5],
        (const float*)d_in[6], (const float*)d_in[7], (const float*)d_in[8], (const int*)d_in[9],
        (float*)d_out);
}

// round 16
// speedup vs baseline: 1.1595x; 1.1595x over previous
#include <cuda_runtime.h>
#include <cstdint>
#include <math.h>

#define B_   16
#define T_   512
#define P_   2048
#define SN   256
#define SD   1024
#define NC_DEN 128
#define NC_NUM 8
#define NCTA (NC_DEN + NC_NUM)
#define NTHR 256
#define RSMASK 7            // rescale when (t & RSMASK) == 0

// -------------------- persistent device scratch (no runtime allocation) -----
__device__ __align__(16) float g_qden[2][SD * 16];
__device__ __align__(16) float g_qnum[2][SN * 16];
__device__ float g_part[NCTA][16];
__device__ double g_lp[2][16];
__device__ unsigned long long g_bar;   // monotonic; survives graph replays

__device__ __forceinline__ unsigned long long ld_relaxed_u64(const unsigned long long* p) {
    unsigned long long v;
    asm volatile("ld.relaxed.gpu.u64 %0, [%1];" : "=l"(v) : "l"(p));
    return v;
}

// -------------------- grid barrier (136 CTAs co-resident) -------------------
__device__ __forceinline__ void grid_barrier() {
    __syncthreads();
    if (threadIdx.x == 0) {
        __threadfence();
        unsigned long long old = atomicAdd(&g_bar, 1ULL);
        unsigned long long target = (old / NCTA + 1ULL) * (unsigned long long)NCTA;
        while (ld_relaxed_u64(&g_bar) < target) { }
        __threadfence();
    }
    __syncthreads();
}

// -------------------- packed f32x2 helpers -----------------------------------
__device__ __forceinline__ void fma2(long long& a, long long q, long long e) {
    asm("fma.rn.f32x2 %0, %1, %2, %0;" : "+l"(a) : "l"(q), "l"(e));
}
__device__ __forceinline__ void add2(long long& a, long long bb) {
    asm("add.rn.f32x2 %0, %1, %0;" : "+l"(a) : "l"(bb));
}

// -------------------- one FSM (num or den), one column tile per CTA ---------
// q layout in global: q[i*16 + b]; longlong2 index = i*4 + bqg
// thread = (jq, iseg, bqg): tid = jq*64 + iseg*4 + bqg
//   owns b = bqg*4..+4, j = jq*8..+8, i = iseg + NSEG*ii (ii<16, strided!)
template <int S, int JT, int NJQ, int PROB>
__device__ void run_fsm(const float* __restrict__ input,
                        const int*   __restrict__ seqlen,
                        const float* __restrict__ initv,
                        const float* __restrict__ trans,
                        const float* __restrict__ finalv,
                        const int*   __restrict__ pdf,
                        float* q0buf, float* q1buf,
                        int tileIdx, bool tracker, int ctaFirst, int nCtaProb)
{
    constexpr int ILEN  = 16;
    constexpr int NSEG  = S / ILEN;           // den 64, num 16
    constexpr int NOUT  = 16 * JT;            // den 128, num 512
    constexpr int ROWP  = NOUT + 8;           // den 136, num 520
    constexpr int OPT   = (NOUT + NTHR - 1) / NTHR;  // den 1, num 2
    constexpr int EROW  = 2 * JT;             // dup words per i row (16 / 64)
    constexpr int PMASK = JT / 2 - 1;         // 3 / 15
    constexpr int NSW   = (NSEG * 4) / 32;    // warps holding s partials (8 / 2)

    const int tid   = threadIdx.x;
    const int lane  = tid & 31;
    const int warp  = tid >> 5;
    const int jbase = tileIdx * JT;

    extern __shared__ float sm[];
    float* Es  = sm;                           // 16384 words (S*JT*2, both FSMs)
    float* red = sm + 16384;                   // up to 8704 words
    float* ssw = red + 8704;                   // 256 words (warps x 16 b)
    int*   sm_len = (int*)(ssw + 256);         // 16 ints

    if (tid < 16) sm_len[tid] = seqlen[tid];

    // ---- E tile, {e,e} pairs, per-row rotated j-pair slots (conflict-free) --
    for (int k = tid; k < S * JT; k += NTHR) {
        int i = k / JT, jl = k % JT;
        float e = expf(__ldg(&trans[(size_t)i * S + jbase + jl]));
        int rot = (NJQ == 1) ? ((i >> 1) & PMASK) : (i & PMASK);
        int slot = (((jl >> 1) + rot) & PMASK);
        int w = i * EROW + slot * 4 + (jl & 1) * 2;
        Es[w] = e; Es[w + 1] = e;
    }

    // output threads: out = tid + o*NTHR -> (b = out&15, j = out>>4)
    int pdfj[OPT]; int jgA[OPT];
    float qlast[OPT];
    #pragma unroll
    for (int o = 0; o < OPT; o++) {
        int out = tid + o * NTHR;
        if (out < NOUT) {
            int b = out & 15;
            jgA[o] = jbase + (out >> 4);
            pdfj[o] = __ldg(&pdf[jgA[o]]);
            qlast[o] = expf(__ldg(&initv[jgA[o]]) +
                            __ldg(&input[(size_t)b * T_ * P_ + pdfj[o]]));
            __stcg(&q0buf[(size_t)jbase * 16 + out], qlast[o]);
        }
    }

    double Creg = 0.0;                         // tracker-only log-offset

    const int jq   = (NJQ == 1) ? 0 : (tid >> 6);
    const int iseg = (tid >> 2) & (NSEG - 1);
    const int bqg  = tid & 3;

    for (int t = 1; t < T_; ++t) {
        // prefetch this step's emissions BEFORE the barrier
        float ev[OPT];
        #pragma unroll
        for (int o = 0; o < OPT; o++) {
            int out = tid + o * NTHR;
            ev[o] = (out < NOUT)
                  ? __ldg(&input[((size_t)(out & 15) * T_ + t) * P_ + pdfj[o]])
                  : 0.f;
        }

        grid_barrier();                        // q(t-1) globally visible
        const float* qprev = (t & 1) ? q0buf : q1buf;
        float*       qcur  = (t & 1) ? q1buf : q0buf;
        const bool rsc = ((t & RSMASK) == 0);

        long long acA[8], acB[8];
        #pragma unroll
        for (int j = 0; j < 8; j++) { acA[j] = 0; acB[j] = 0; }
        long long sA = 0, sB = 0;
        const longlong2* qp = (const longlong2*)qprev;

        #pragma unroll
        for (int ii = 0; ii < ILEN; ii++) {
            int i = iseg + NSEG * ii;
            longlong2 qv = __ldcg(qp + i * 4 + bqg);
            const float* er = Es + i * EROW;
            int rot = (NJQ == 1) ? ((i >> 1) & PMASK) : (i & PMASK);
            #pragma unroll
            for (int p = 0; p < 4; p++) {
                int slot = ((jq * 4 + p + rot) & PMASK);
                longlong2 e2 = *(const longlong2*)(er + slot * 4);
                fma2(acA[2 * p],     qv.x, e2.x); fma2(acB[2 * p],     qv.y, e2.x);
                fma2(acA[2 * p + 1], qv.x, e2.y); fma2(acB[2 * p + 1], qv.y, e2.y);
            }
            if (rsc) { add2(sA, qv.x); add2(sB, qv.y); }
        }

        // s partials (rescale steps): reduce isegs within warp, store per warp
        if (rsc && (NJQ == 1 || jq == 0)) {
            unsigned long long uA = (unsigned long long)sA, uB = (unsigned long long)sB;
            #pragma unroll
            for (int m = 4; m < 32; m <<= 1) {
                long long tA = (long long)__shfl_xor_sync(0xffffffffu, uA, m);
                long long tB = (long long)__shfl_xor_sync(0xffffffffu, uB, m);
                add2((long long&)uA, tA); add2((long long&)uB, tB);
            }
            if (lane < 4) {
                *(long long*)&ssw[warp * 16 + lane * 4]     = (long long)uA;
                *(long long*)&ssw[warp * 16 + lane * 4 + 2] = (long long)uB;
            }
        }

        // store partials: red[iseg][(jq*8+jl)*16 + bqg*4 .. +3]
        {
            float* rb = red + iseg * ROWP + (jq * 8) * 16 + bqg * 4;
            #pragma unroll
            for (int j = 0; j < 8; j++) {
                longlong2 v; v.x = acA[j]; v.y = acB[j];
                *(longlong2*)(rb + j * 16) = v;
            }
        }
        __syncthreads();

        // stage A + q update (out threads reduce all NSEG segments directly)
        #pragma unroll
        for (int o = 0; o < OPT; o++) {
            int out = tid + o * NTHR;
            if (out < NOUT) {
                const float* rr = red + out;
                float dot = 0.f;
                #pragma unroll
                for (int s2 = 0; s2 < NSEG; s2++) dot += rr[s2 * ROWP];
                int b = out & 15;
                float qn;
                if (rsc) {
                    float s = 0.f;
                    #pragma unroll
                    for (int w2 = 0; w2 < NSW; w2++) s += ssw[w2 * 16 + b];
                    float inv = 1.0f / s;
                    qn = (t < sm_len[b]) ? dot * inv * expf(ev[o]) : qlast[o] * inv;
                    if (tracker && out < 16) Creg += (double)logf(s);
                } else {
                    qn = (t < sm_len[b]) ? dot * expf(ev[o]) : qlast[o];
                }
                qlast[o] = qn;
                __stcg(&qcur[(size_t)jbase * 16 + out], qn);
            }
        }
    }

    // ---------------- final: logprob_b = C_b + log( sum_j q_T[b,j]*exp(final_j) )
    __syncthreads();
    #pragma unroll
    for (int o = 0; o < OPT; o++) {
        int out = tid + o * NTHR;
        if (out < NOUT) red[out] = qlast[o] * expf(__ldg(&finalv[jgA[o]]));
    }
    __syncthreads();
    if (tid < 16) {
        float p = 0.f;
        #pragma unroll
        for (int c = 0; c < JT; c++) p += red[c * 16 + tid];
        g_part[blockIdx.x][tid] = p;
    }
    __threadfence();
    grid_barrier();
    if (tracker && tid < 16) {
        double tot = 0.0;
        for (int c = 0; c < nCtaProb; c++)
            tot += (double)__ldcg(&g_part[ctaFirst + c][tid]);
        g_lp[PROB][tid] = Creg + log(tot);
    }
    __threadfence();
    grid_barrier();
}

// -------------------- kernel ------------------------------------------------
__global__ void __launch_bounds__(NTHR, 1)
lfmmi_kernel(const float* input, const int* seqlen,
             const float* n_init, const float* n_trans, const float* n_final, const int* n_pdf,
             const float* d_init, const float* d_trans, const float* d_final, const int* d_pdf,
             float* out)
{
    int cta = blockIdx.x;
    if (cta < NC_DEN) {
        run_fsm<SD, 8, 1, 0>(input, seqlen, d_init, d_trans, d_final, d_pdf,
                             g_qden[0], g_qden[1], cta, cta == 0, 0, NC_DEN);
    } else {
        run_fsm<SN, 32, 4, 1>(input, seqlen, n_init, n_trans, n_final, n_pdf,
                              g_qnum[0], g_qnum[1], cta - NC_DEN, cta == NC_DEN,
                              NC_DEN, NC_NUM);
    }
    if (cta == 0 && threadIdx.x == 0) {
        double dsum = 0.0, nsum = 0.0;
        for (int bb = 0; bb < 16; ++bb) {
            dsum += __ldcg(&g_lp[0][bb]);
            nsum += __ldcg(&g_lp[1][bb]);
        }
        out[0] = (float)(-(nsum - dsum));
    }
}

// -------------------- launch -------------------------------------------------
extern "C" void kernel_launch(void* const* d_in, const int* in_sizes, int n_in,
                              void* d_out, int out_size)
{
    (void)in_sizes; (void)n_in; (void)out_size;
    // words: Es 16384 + red 8704 + ssw 256 + len 16 = 25360
    const size_t smem = 25360 * sizeof(float);   // 101,440 B
    cudaFuncSetAttribute(lfmmi_kernel,
                         cudaFuncAttributeMaxDynamicSharedMemorySize, (int)smem);
    lfmmi_kernel<<<NCTA, NTHR, smem>>>(
        (const float*)d_in[0], (const int*)d_in[1],
        (const float*)d_in[2], (const float*)d_in[3], (const float*)d_in[4], (const int*)d_in[5],
        (const float*)d_in[6], (const float*)d_in[7], (const float*)d_in[8], (const int*)d_in[9],
        (float*)d_out);
}

// round 17
// speedup vs baseline: 1.1929x; 1.0287x over previous
#include <cuda_runtime.h>
#include <cstdint>
#include <math.h>

#define B_   16
#define T_   512
#define P_   2048
#define SN   256
#define SD   1024
#define NC_DEN 128
#define NC_NUM 8
#define NCTA (NC_DEN + NC_NUM)
#define NTHR 512
#define RSMASK 7            // rescale when (t & RSMASK) == 0

// -------------------- persistent device scratch (no runtime allocation) -----
__device__ __align__(16) float g_qden[2][SD * 16];
__device__ __align__(16) float g_qnum[2][SN * 16];
__device__ float g_part[NCTA][16];
__device__ double g_lp[2][16];
__device__ unsigned long long g_bar;   // monotonic; survives graph replays

__device__ __forceinline__ unsigned long long ld_relaxed_u64(const unsigned long long* p) {
    unsigned long long v;
    asm volatile("ld.relaxed.gpu.u64 %0, [%1];" : "=l"(v) : "l"(p));
    return v;
}

// -------------------- grid barrier (136 CTAs co-resident) -------------------
__device__ __forceinline__ void grid_barrier() {
    __syncthreads();
    if (threadIdx.x == 0) {
        __threadfence();
        unsigned long long old = atomicAdd(&g_bar, 1ULL);
        unsigned long long target = (old / NCTA + 1ULL) * (unsigned long long)NCTA;
        while (ld_relaxed_u64(&g_bar) < target) { }
        __threadfence();
    }
    __syncthreads();
}

// -------------------- packed f32x2 helpers -----------------------------------
__device__ __forceinline__ void fma2(long long& a, long long q, long long e) {
    asm("fma.rn.f32x2 %0, %1, %2, %0;" : "+l"(a) : "l"(q), "l"(e));
}
__device__ __forceinline__ void add2(long long& a, long long bb) {
    asm("add.rn.f32x2 %0, %1, %0;" : "+l"(a) : "l"(bb));
}

// -------------------- one FSM (num or den), one column tile per CTA ---------
// q layout in global: q[i*16 + b]; longlong2 index = i*4 + bqg
// den: tid = iseg*4 + bqg          (jq = 0,   NSEG = 128, ILEN = 8,  8 j/thr)
// num: tid = jq*64 + iseg*4 + bqg  (jq = 0-7, NSEG = 16,  ILEN = 16, 4 j/thr)
template <int S, int JT, int NJQ, int PROB>
__device__ void run_fsm(const float* __restrict__ input,
                        const int*   __restrict__ seqlen,
                        const float* __restrict__ initv,
                        const float* __restrict__ trans,
                        const float* __restrict__ finalv,
                        const int*   __restrict__ pdf,
                        float* q0buf, float* q1buf,
                        int tileIdx, bool tracker, int ctaFirst, int nCtaProb)
{
    constexpr int JTH   = JT / NJQ;           // j's per thread: den 8, num 4
    constexpr int NSEG  = NTHR / (4 * NJQ);   // den 128, num 16
    constexpr int ILEN  = S / NSEG;           // den 8,  num 16
    constexpr int NOUT  = 16 * JT;            // den 128, num 512
    constexpr int ROWP  = NOUT + 8;           // den 136, num 520
    constexpr int SPLIT = NTHR / NOUT;        // den 4,  num 1
    constexpr int SEGPT = NSEG / SPLIT;       // den 32, num 16
    constexpr int EROW  = 2 * JT;             // den 16, num 64
    constexpr int PMASK = JT / 2 - 1;         // den 3,  num 15
    constexpr int NSW   = (NJQ == 1) ? 16 : 2; // warps holding s partials

    const int tid   = threadIdx.x;
    const int lane  = tid & 31;
    const int warp  = tid >> 5;
    const int jbase = tileIdx * JT;

    extern __shared__ float sm[];
    float* Es   = sm;                          // 16384 words (S*JT*2, both FSMs)
    float* red  = sm + 16384;                  // up to 17408 words (NSEG*ROWP)
    float* part = red + 17408;                 // 544 words
    float* ssw  = part + 544;                  // 256 words (warps x 16 b)
    int*   sm_len = (int*)(ssw + 256);         // 16 ints

    if (tid < 16) sm_len[tid] = seqlen[tid];

    // ---- E tile, {e,e} pairs, per-row rotated j-pair slots (conflict-free) --
    for (int k = tid; k < S * JT; k += NTHR) {
        int i = k / JT, jl = k % JT;
        float e = expf(__ldg(&trans[(size_t)i * S + jbase + jl]));
        int rot  = (NJQ == 1) ? ((i >> 1) & PMASK) : (i & PMASK);
        int slot = ((jl >> 1) + rot) & PMASK;
        int w = i * EROW + slot * 4 + (jl & 1) * 2;
        Es[w] = e; Es[w + 1] = e;
    }

    // output threads: out = tid (< NOUT) -> (b = out&15, j = out>>4)
    int pdfj = 0, jg = 0;
    float qlast = 0.f;
    if (tid < NOUT) {
        int b = tid & 15;
        jg = jbase + (tid >> 4);
        pdfj = __ldg(&pdf[jg]);
        qlast = expf(__ldg(&initv[jg]) + __ldg(&input[(size_t)b * T_ * P_ + pdfj]));
        __stcg(&q0buf[(size_t)jbase * 16 + tid], qlast);
    }

    double Creg = 0.0;                         // tracker-only log-offset

    const int jq   = (NJQ == 1) ? 0 : (tid >> 6);
    const int iseg = (tid >> 2) & (NSEG - 1);
    const int bqg  = tid & 3;

    for (int t = 1; t < T_; ++t) {
        // prefetch this step's emission BEFORE the barrier
        float ev = 0.f;
        if (tid < NOUT) ev = __ldg(&input[((size_t)(tid & 15) * T_ + t) * P_ + pdfj]);

        grid_barrier();                        // q(t-1) globally visible
        const float* qprev = (t & 1) ? q0buf : q1buf;
        float*       qcur  = (t & 1) ? q1buf : q0buf;
        const bool rsc = ((t & RSMASK) == 0);

        long long acA[JTH], acB[JTH];
        #pragma unroll
        for (int j = 0; j < JTH; j++) { acA[j] = 0; acB[j] = 0; }
        long long sA = 0, sB = 0;
        const longlong2* qp = (const longlong2*)qprev;

        #pragma unroll
        for (int ii = 0; ii < ILEN; ii++) {
            int i = iseg + NSEG * ii;
            longlong2 qv = __ldcg(qp + i * 4 + bqg);
            const float* er = Es + i * EROW;
            int rot = (NJQ == 1) ? ((i >> 1) & PMASK) : (i & PMASK);
            #pragma unroll
            for (int p = 0; p < JTH / 2; p++) {
                int slot = (jq * (JTH / 2) + p + rot) & PMASK;
                longlong2 e2 = *(const longlong2*)(er + slot * 4);
                fma2(acA[2 * p],     qv.x, e2.x); fma2(acB[2 * p],     qv.y, e2.x);
                fma2(acA[2 * p + 1], qv.x, e2.y); fma2(acB[2 * p + 1], qv.y, e2.y);
            }
            if (rsc) { add2(sA, qv.x); add2(sB, qv.y); }
        }

        // s partials (rescale steps): butterfly isegs within warp, one row/warp
        if (rsc && (NJQ == 1 || jq == 0)) {
            unsigned long long uA = (unsigned long long)sA, uB = (unsigned long long)sB;
            #pragma unroll
            for (int m = 4; m < 32; m <<= 1) {
                long long tA = (long long)__shfl_xor_sync(0xffffffffu, uA, m);
                long long tB = (long long)__shfl_xor_sync(0xffffffffu, uB, m);
                add2((long long&)uA, tA); add2((long long&)uB, tB);
            }
            if (lane < 4) {
                *(long long*)&ssw[warp * 16 + lane * 4]     = (long long)uA;
                *(long long*)&ssw[warp * 16 + lane * 4 + 2] = (long long)uB;
            }
        }

        // store partials: red[iseg][(jq*JTH+jl)*16 + bqg*4 .. +3]
        {
            float* rb = red + iseg * ROWP + (jq * JTH) * 16 + bqg * 4;
            #pragma unroll
            for (int j = 0; j < JTH; j++) {
                longlong2 v; v.x = acA[j]; v.y = acB[j];
                *(longlong2*)(rb + j * 16) = v;
            }
        }
        __syncthreads();

        // stage A: two-level segment reduction
        float dot = 0.f;
        {
            int out = tid & (NOUT - 1), g2 = tid / NOUT;
            const float* rr = red + (g2 * SEGPT) * ROWP + out;
            float p = 0.f;
            #pragma unroll
            for (int s2 = 0; s2 < SEGPT; s2++) p += rr[s2 * ROWP];
            if (SPLIT > 1) part[g2 * 136 + out] = p; else dot = p;
        }
        if (SPLIT > 1) {
            __syncthreads();
            if (tid < NOUT) {
                dot = part[tid];
                #pragma unroll
                for (int g = 1; g < SPLIT; g++) dot += part[g * 136 + tid];
            }
        }

        // q(t) update; rescale every 8 steps
        if (tid < NOUT) {
            int b = tid & 15;
            float qn;
            if (rsc) {
                float s = 0.f;
                #pragma unroll
                for (int w2 = 0; w2 < NSW; w2++) s += ssw[w2 * 16 + b];
                float inv = 1.0f / s;
                qn = (t < sm_len[b]) ? dot * inv * expf(ev) : qlast * inv;
                if (tracker && tid < 16) Creg += (double)logf(s);
            } else {
                qn = (t < sm_len[b]) ? dot * expf(ev) : qlast;
            }
            qlast = qn;
            __stcg(&qcur[(size_t)jbase * 16 + tid], qn);
        }
    }

    // ---------------- final: logprob_b = C_b + log( sum_j q_T[b,j]*exp(final_j) )
    __syncthreads();
    if (tid < NOUT) red[tid] = qlast * expf(__ldg(&finalv[jg]));
    __syncthreads();
    if (tid < 16) {
        float p = 0.f;
        #pragma unroll
        for (int c = 0; c < JT; c++) p += red[c * 16 + tid];
        g_part[blockIdx.x][tid] = p;
    }
    __threadfence();
    grid_barrier();
    if (tracker && tid < 16) {
        double tot = 0.0;
        for (int c = 0; c < nCtaProb; c++)
            tot += (double)__ldcg(&g_part[ctaFirst + c][tid]);
        g_lp[PROB][tid] = Creg + log(tot);
    }
    __threadfence();
    grid_barrier();
}

// -------------------- kernel ------------------------------------------------
__global__ void __launch_bounds__(NTHR, 1)
lfmmi_kernel(const float* input, const int* seqlen,
             const float* n_init, const float* n_trans, const float* n_final, const int* n_pdf,
             const float* d_init, const float* d_trans, const float* d_final, const int* d_pdf,
             float* out)
{
    int cta = blockIdx.x;
    if (cta < NC_DEN) {
        run_fsm<SD, 8, 1, 0>(input, seqlen, d_init, d_trans, d_final, d_pdf,
                             g_qden[0], g_qden[1], cta, cta == 0, 0, NC_DEN);
    } else {
        run_fsm<SN, 32, 8, 1>(input, seqlen, n_init, n_trans, n_final, n_pdf,
                              g_qnum[0], g_qnum[1], cta - NC_DEN, cta == NC_DEN,
                              NC_DEN, NC_NUM);
    }
    if (cta == 0 && threadIdx.x == 0) {
        double dsum = 0.0, nsum = 0.0;
        for (int bb = 0; bb < 16; ++bb) {
            dsum += __ldcg(&g_lp[0][bb]);
            nsum += __ldcg(&g_lp[1][bb]);
        }
        out[0] = (float)(-(nsum - dsum));
    }
}

// -------------------- launch -------------------------------------------------
extern "C" void kernel_launch(void* const* d_in, const int* in_sizes, int n_in,
                              void* d_out, int out_size)
{
    (void)in_sizes; (void)n_in; (void)out_size;
    // words: Es 16384 + red 17408 + part 544 + ssw 256 + len 16 = 34608
    const size_t smem = 34608 * sizeof(float);   // 138,432 B
    cudaFuncSetAttribute(lfmmi_kernel,
                         cudaFuncAttributeMaxDynamicSharedMemorySize, (int)smem);
    lfmmi_kernel<<<NCTA, NTHR, smem>>>(
        (const float*)d_in[0], (const int*)d_in[1],
        (const float*)d_in[2], (const float*)d_in[3], (const float*)d_in[4], (const int*)d_in[5],
        (const float*)d_in[6], (const float*)d_in[7], (const float*)d_in[8], (const int*)d_in[9],
        (float*)d_out);
}